// round 1
// baseline (speedup 1.0000x reference)
#include <cuda_runtime.h>

#define B_    16
#define TQ_   128
#define TK_   128
#define EMB_  256
#define HID_  100
#define F2E_  512   // 2*EMB

// Scratch (allocation-free rule: __device__ globals)
__device__ float g_A[B_ * TK_ * HID_];        // A[b][i][h]
__device__ float g_Ct[B_ * HID_ * TQ_];       // C^T[b][h][j]  (includes +b1)
__device__ float g_feat[B_ * TK_ * F2E_];     // [row][f]  f<256: mul, f>=256: sub^2

__device__ __forceinline__ float ftanh(float x) {
    // tanh(x) = 1 - 2/(e^{2x}+1); exact at +-inf limits, rel err ~1e-6
    float e = __expf(2.0f * x);
    return 1.0f - __fdividef(2.0f, e + 1.0f);
}

// ---------------------------------------------------------------------------
// K1: A[b,i,h] = keys[b,i,:] . W1[h, :E]
//     Ct[b,h,j] = queries[b,j,:] . W1[h, E:] + b1[h]
// grid: 2*B*T blocks of 128 threads; one output row per block.
// ---------------------------------------------------------------------------
__global__ void prep_kernel(const float* __restrict__ queries,
                            const float* __restrict__ keys,
                            const float* __restrict__ W1,
                            const float* __restrict__ b1) {
    __shared__ float x_s[EMB_];
    int bx = blockIdx.x;
    bool isA = bx < B_ * TK_;
    int row = bx & (B_ * TK_ - 1);
    const float* x = (isA ? keys : queries) + row * EMB_;
    int tid = threadIdx.x;
    x_s[tid] = x[tid];
    x_s[tid + 128] = x[tid + 128];
    __syncthreads();

    int w = tid >> 5, lane = tid & 31;
    for (int it = 0; it < 25; ++it) {          // 25 iters * 4 warps = 100 h
        int h = it * 4 + w;
        const float* Wrow = W1 + h * F2E_ + (isA ? 0 : EMB_);
        float acc = 0.f;
        #pragma unroll
        for (int k = 0; k < 8; ++k) {
            int e = lane + 32 * k;
            acc = fmaf(x_s[e], Wrow[e], acc);
        }
        #pragma unroll
        for (int off = 16; off; off >>= 1)
            acc += __shfl_xor_sync(0xffffffffu, acc, off);
        if (lane == 0) {
            if (isA) {
                g_A[row * HID_ + h] = acc;
            } else {
                int b = row >> 7, j = row & 127;
                g_Ct[(b * HID_ + h) * TQ_ + j] = acc + b1[h];
            }
        }
    }
}

// ---------------------------------------------------------------------------
// K2: fused score MLP + softmax + attention + feature build.
// One block per (b, 16-row i-tile): grid (8, 16), 256 threads.
// smem: c_s[100][128] + a_s[16][100] + p_s[128][20] + w2 + km
// ---------------------------------------------------------------------------
#define PSTR 20   // p_s row stride (floats): 80B, 16B aligned, 4-way-max conflicts

__global__ void attn_kernel(const float* __restrict__ queries,
                            const float* __restrict__ keys,
                            const float* __restrict__ qmask,
                            const float* __restrict__ kmask,
                            const float* __restrict__ W2) {
    extern __shared__ float sm[];
    float* c_s  = sm;                       // 12800
    float* a_s  = c_s + HID_ * TQ_;         // 1600
    float* p_s  = a_s + 16 * HID_;          // 128*20 = 2560 (16B aligned offset)
    float* w2_s = p_s + TQ_ * PSTR;         // 104
    float* km_s = w2_s + 104;               // 16

    int b  = blockIdx.y;
    int i0 = blockIdx.x * 16;
    int tid = threadIdx.x;

    for (int idx = tid; idx < HID_ * TQ_; idx += 256)
        c_s[idx] = g_Ct[b * HID_ * TQ_ + idx];
    for (int idx = tid; idx < 16 * HID_; idx += 256)
        a_s[idx] = g_A[(b * TK_ + i0) * HID_ + idx];
    if (tid < HID_) w2_s[tid] = W2[tid];
    if (tid < 16)   km_s[tid] = kmask[b * TK_ + tid + i0];

    int j = tid & 127;        // query position
    int g = tid >> 7;         // i-row group (0/1)
    float qm = qmask[b * TQ_ + j];
    __syncthreads();

    // ---- phase 1: sim[ii][j] = sum_h tanh(a[ii,h] + c[h,j]) * w2[h]
    float acc[8];
    #pragma unroll
    for (int r = 0; r < 8; ++r) acc[r] = 0.f;
    for (int h = 0; h < HID_; ++h) {
        float cj = c_s[h * TQ_ + j];
        float w  = w2_s[h];
        #pragma unroll
        for (int r = 0; r < 8; ++r) {
            float x = a_s[(g + 2 * r) * HID_ + h] + cj;
            acc[r] = fmaf(w, ftanh(x), acc[r]);
        }
    }
    const float NEGC = -4294967295.0f;  // -2^32 + 1
    #pragma unroll
    for (int r = 0; r < 8; ++r) {
        float s = (qm == 0.0f) ? NEGC : acc[r];
        p_s[j * PSTR + (g + 2 * r)] = s;
    }
    __syncthreads();

    // ---- phase 2: softmax over j per row ii; warp w owns rows 2w, 2w+1
    int warp = tid >> 5, lane = tid & 31;
    #pragma unroll
    for (int rr = 0; rr < 2; ++rr) {
        int ii = 2 * warp + rr;
        float v[4];
        float m = -3.4e38f;
        #pragma unroll
        for (int q = 0; q < 4; ++q) {
            v[q] = p_s[(lane + 32 * q) * PSTR + ii];
            m = fmaxf(m, v[q]);
        }
        #pragma unroll
        for (int off = 16; off; off >>= 1)
            m = fmaxf(m, __shfl_xor_sync(0xffffffffu, m, off));
        float ssum = 0.f;
        #pragma unroll
        for (int q = 0; q < 4; ++q) { v[q] = __expf(v[q] - m); ssum += v[q]; }
        #pragma unroll
        for (int off = 16; off; off >>= 1)
            ssum += __shfl_xor_sync(0xffffffffu, ssum, off);
        float scale = km_s[ii] / ssum;   // fold key_mask scalar into p
        #pragma unroll
        for (int q = 0; q < 4; ++q)
            p_s[(lane + 32 * q) * PSTR + ii] = v[q] * scale;
    }
    __syncthreads();

    // ---- phase 3: keys_attn[ii,e] = sum_j p[ii,j] * q[b,j,e]; then features
    int e = tid;  // 0..255
    float ka[16];
    #pragma unroll
    for (int r = 0; r < 16; ++r) ka[r] = 0.f;
    const float* qb = queries + b * TQ_ * EMB_ + e;
    #pragma unroll 2
    for (int jj = 0; jj < TQ_; ++jj) {
        float qv = qb[jj * EMB_];
        float pv[16];
        *(float4*)&pv[0]  = *(const float4*)&p_s[jj * PSTR + 0];
        *(float4*)&pv[4]  = *(const float4*)&p_s[jj * PSTR + 4];
        *(float4*)&pv[8]  = *(const float4*)&p_s[jj * PSTR + 8];
        *(float4*)&pv[12] = *(const float4*)&p_s[jj * PSTR + 12];
        #pragma unroll
        for (int r = 0; r < 16; ++r)
            ka[r] = fmaf(pv[r], qv, ka[r]);
    }
    #pragma unroll
    for (int r = 0; r < 16; ++r) {
        int rowg = b * TK_ + i0 + r;
        float kv = keys[rowg * EMB_ + e];
        float fm = ka[r] * kv;
        float d  = ka[r] - kv;
        g_feat[rowg * F2E_ + e]        = fm;
        g_feat[rowg * F2E_ + EMB_ + e] = d * d;
    }
}

// ---------------------------------------------------------------------------
// K3: out[2048,256] = relu(feat[2048,512] @ Wlast[256,512]^T + blast)
// BM=BN=64, BK=32, 256 threads, 4x4 micro-tiles.
// ---------------------------------------------------------------------------
__global__ void gemm_kernel(const float* __restrict__ Wlast,
                            const float* __restrict__ blast,
                            float* __restrict__ out) {
    __shared__ float As[32 * 65];
    __shared__ float Bs[32 * 65];
    int m0 = blockIdx.y * 64;
    int n0 = blockIdx.x * 64;
    int tid = threadIdx.x;
    int tx = tid & 15, ty = tid >> 4;

    float acc[4][4];
    #pragma unroll
    for (int i = 0; i < 4; ++i)
        #pragma unroll
        for (int jq = 0; jq < 4; ++jq) acc[i][jq] = 0.f;

    int lc = tid & 31, lr = tid >> 5;  // k-lane, row-group
    for (int k0 = 0; k0 < F2E_; k0 += 32) {
        #pragma unroll
        for (int r = lr; r < 64; r += 8)
            As[lc * 65 + r] = g_feat[(m0 + r) * F2E_ + k0 + lc];
        #pragma unroll
        for (int r = lr; r < 64; r += 8)
            Bs[lc * 65 + r] = Wlast[(n0 + r) * F2E_ + k0 + lc];
        __syncthreads();
        #pragma unroll
        for (int k = 0; k < 32; ++k) {
            float av[4], bv[4];
            #pragma unroll
            for (int q = 0; q < 4; ++q) av[q] = As[k * 65 + ty * 4 + q];
            #pragma unroll
            for (int q = 0; q < 4; ++q) bv[q] = Bs[k * 65 + tx * 4 + q];
            #pragma unroll
            for (int i = 0; i < 4; ++i)
                #pragma unroll
                for (int jq = 0; jq < 4; ++jq)
                    acc[i][jq] = fmaf(av[i], bv[jq], acc[i][jq]);
        }
        __syncthreads();
    }

    #pragma unroll
    for (int i = 0; i < 4; ++i) {
        int row = m0 + ty * 4 + i;
        float4 o;
        float b0 = blast[n0 + tx * 4 + 0];
        float b1v = blast[n0 + tx * 4 + 1];
        float b2 = blast[n0 + tx * 4 + 2];
        float b3 = blast[n0 + tx * 4 + 3];
        o.x = fmaxf(acc[i][0] + b0, 0.f);
        o.y = fmaxf(acc[i][1] + b1v, 0.f);
        o.z = fmaxf(acc[i][2] + b2, 0.f);
        o.w = fmaxf(acc[i][3] + b3, 0.f);
        *(float4*)&out[row * EMB_ + n0 + tx * 4] = o;
    }
}

// ---------------------------------------------------------------------------
extern "C" void kernel_launch(void* const* d_in, const int* in_sizes, int n_in,
                              void* d_out, int out_size) {
    const float* queries = (const float*)d_in[0];
    const float* keys    = (const float*)d_in[1];
    const float* qmask   = (const float*)d_in[2];
    const float* kmask   = (const float*)d_in[3];
    const float* W1      = (const float*)d_in[4];
    const float* b1      = (const float*)d_in[5];
    const float* W2      = (const float*)d_in[6];
    const float* Wlast   = (const float*)d_in[7];
    const float* blast   = (const float*)d_in[8];
    float* out = (float*)d_out;

    static_assert(sizeof(float) == 4, "");
    const int smem_attn = (HID_ * TQ_ + 16 * HID_ + TQ_ * PSTR + 104 + 16) * 4;
    cudaFuncSetAttribute(attn_kernel, cudaFuncAttributeMaxDynamicSharedMemorySize,
                         smem_attn);

    prep_kernel<<<2 * B_ * TK_, 128>>>(queries, keys, W1, b1);
    attn_kernel<<<dim3(8, B_), 256, smem_attn>>>(queries, keys, qmask, kmask, W2);
    gemm_kernel<<<dim3(EMB_ / 64, (B_ * TK_) / 64), 256>>>(Wlast, blast, out);
}

// round 2
// speedup vs baseline: 1.2899x; 1.2899x over previous
#include <cuda_runtime.h>

#define B_    16
#define TQ_   128
#define TK_   128
#define EMB_  256
#define HID_  100
#define F2E_  512   // 2*EMB

// Scratch (allocation-free rule: __device__ globals)
__device__ float g_A[B_ * TK_ * HID_];        // A[b][i][h]
__device__ float g_Ct[B_ * HID_ * TQ_];       // C^T[b][h][j]  (includes +b1)
__device__ float g_feat[B_ * TK_ * F2E_];     // [row][f]  f<256: mul, f>=256: sub^2

__device__ __forceinline__ float ftanh(float x) {
    float y;
    asm("tanh.approx.f32 %0, %1;" : "=f"(y) : "f"(x));
    return y;
}

// ---------------------------------------------------------------------------
// K1: prep as a tiled GEMM.
//   side 0: A[row,h]  = keys[row,:]    . W1[h, 0:256]
//   side 1: Ct[b,h,j] = queries[row,:] . W1[h, 256:512] + b1[h]   (row=b*128+j)
// BM=64 rows, BN=64 h (2 n-tiles cover H=100 padded), BK=32, 256 thr, 4x4 micro.
// grid (2, 32, 2) = 128 blocks.
// ---------------------------------------------------------------------------
__global__ void prep_gemm(const float* __restrict__ queries,
                          const float* __restrict__ keys,
                          const float* __restrict__ W1,
                          const float* __restrict__ b1) {
    __shared__ float Xs[32 * 65];
    __shared__ float Ws[32 * 65];
    int side = blockIdx.z;                 // 0: keys->A, 1: queries->Ct
    int n0 = blockIdx.x * 64;              // h tile
    int m0 = blockIdx.y * 64;              // row tile
    const float* X = side ? queries : keys;
    const float* Wb = W1 + (side ? EMB_ : 0);

    int tid = threadIdx.x;
    int tx = tid & 15, ty = tid >> 4;
    int lc = tid & 31, lr = tid >> 5;

    float acc[4][4];
    #pragma unroll
    for (int i = 0; i < 4; ++i)
        #pragma unroll
        for (int q = 0; q < 4; ++q) acc[i][q] = 0.f;

    for (int k0 = 0; k0 < EMB_; k0 += 32) {
        #pragma unroll
        for (int r = lr; r < 64; r += 8)
            Xs[lc * 65 + r] = X[(m0 + r) * EMB_ + k0 + lc];
        #pragma unroll
        for (int r = lr; r < 64; r += 8)
            Ws[lc * 65 + r] = (n0 + r < HID_) ? Wb[(n0 + r) * F2E_ + k0 + lc] : 0.f;
        __syncthreads();
        #pragma unroll
        for (int k = 0; k < 32; ++k) {
            float xv[4], wv[4];
            #pragma unroll
            for (int q = 0; q < 4; ++q) xv[q] = Xs[k * 65 + ty * 4 + q];
            #pragma unroll
            for (int q = 0; q < 4; ++q) wv[q] = Ws[k * 65 + tx * 4 + q];
            #pragma unroll
            for (int i = 0; i < 4; ++i)
                #pragma unroll
                for (int q = 0; q < 4; ++q)
                    acc[i][q] = fmaf(xv[i], wv[q], acc[i][q]);
        }
        __syncthreads();
    }

    #pragma unroll
    for (int i = 0; i < 4; ++i) {
        int row = m0 + ty * 4 + i;
        #pragma unroll
        for (int q = 0; q < 4; ++q) {
            int h = n0 + tx * 4 + q;
            if (h < HID_) {
                if (side == 0) {
                    g_A[row * HID_ + h] = acc[i][q];
                } else {
                    int b = row >> 7, j = row & 127;
                    g_Ct[(b * HID_ + h) * TQ_ + j] = acc[i][q] + b1[h];
                }
            }
        }
    }
}

// ---------------------------------------------------------------------------
// K2: fused score MLP + softmax + attention + feature build.
// One block per (b, 16-row i-tile): grid (8, 16), 256 threads.
// ---------------------------------------------------------------------------
#define PSTR 20   // p_s row stride (floats)

__global__ void attn_kernel(const float* __restrict__ queries,
                            const float* __restrict__ keys,
                            const float* __restrict__ qmask,
                            const float* __restrict__ kmask,
                            const float* __restrict__ W2) {
    extern __shared__ float sm[];
    float* c_s  = sm;                       // 12800
    float* a_s  = c_s + HID_ * TQ_;         // 1600
    float* p_s  = a_s + 16 * HID_;          // 2560
    float* w2_s = p_s + TQ_ * PSTR;         // 104
    float* km_s = w2_s + 104;               // 16

    int b  = blockIdx.y;
    int i0 = blockIdx.x * 16;
    int tid = threadIdx.x;

    for (int idx = tid; idx < HID_ * TQ_; idx += 256)
        c_s[idx] = g_Ct[b * HID_ * TQ_ + idx];
    for (int idx = tid; idx < 16 * HID_; idx += 256)
        a_s[idx] = g_A[(b * TK_ + i0) * HID_ + idx];
    if (tid < HID_) w2_s[tid] = W2[tid];
    if (tid < 16)   km_s[tid] = kmask[b * TK_ + tid + i0];

    int j = tid & 127;        // query position
    int g = tid >> 7;         // i-row group (0/1)
    float qm = qmask[b * TQ_ + j];
    __syncthreads();

    // ---- phase 1: sim[ii][j] = sum_h tanh(a[ii,h] + c[h,j]) * w2[h]
    float acc[8];
    #pragma unroll
    for (int r = 0; r < 8; ++r) acc[r] = 0.f;
    for (int h = 0; h < HID_; ++h) {
        float cj = c_s[h * TQ_ + j];
        float w  = w2_s[h];
        #pragma unroll
        for (int r = 0; r < 8; ++r) {
            float x = a_s[(g + 2 * r) * HID_ + h] + cj;
            acc[r] = fmaf(w, ftanh(x), acc[r]);
        }
    }
    const float NEGC = -4294967295.0f;  // -2^32 + 1
    #pragma unroll
    for (int r = 0; r < 8; ++r) {
        float s = (qm == 0.0f) ? NEGC : acc[r];
        p_s[j * PSTR + (g + 2 * r)] = s;
    }
    __syncthreads();

    // ---- phase 2: softmax over j per row ii; warp w owns rows 2w, 2w+1
    int warp = tid >> 5, lane = tid & 31;
    #pragma unroll
    for (int rr = 0; rr < 2; ++rr) {
        int ii = 2 * warp + rr;
        float v[4];
        float m = -3.4e38f;
        #pragma unroll
        for (int q = 0; q < 4; ++q) {
            v[q] = p_s[(lane + 32 * q) * PSTR + ii];
            m = fmaxf(m, v[q]);
        }
        #pragma unroll
        for (int off = 16; off; off >>= 1)
            m = fmaxf(m, __shfl_xor_sync(0xffffffffu, m, off));
        float ssum = 0.f;
        #pragma unroll
        for (int q = 0; q < 4; ++q) { v[q] = __expf(v[q] - m); ssum += v[q]; }
        #pragma unroll
        for (int off = 16; off; off >>= 1)
            ssum += __shfl_xor_sync(0xffffffffu, ssum, off);
        float scale = km_s[ii] / ssum;   // fold key_mask scalar into p
        #pragma unroll
        for (int q = 0; q < 4; ++q)
            p_s[(lane + 32 * q) * PSTR + ii] = v[q] * scale;
    }
    __syncthreads();

    // ---- phase 3: keys_attn[ii,e] = sum_j p[ii,j] * q[b,j,e]; then features
    int e = tid;  // 0..255
    float ka[16];
    #pragma unroll
    for (int r = 0; r < 16; ++r) ka[r] = 0.f;
    const float* qb = queries + b * TQ_ * EMB_ + e;
    #pragma unroll 2
    for (int jj = 0; jj < TQ_; ++jj) {
        float qv = qb[jj * EMB_];
        float pv[16];
        *(float4*)&pv[0]  = *(const float4*)&p_s[jj * PSTR + 0];
        *(float4*)&pv[4]  = *(const float4*)&p_s[jj * PSTR + 4];
        *(float4*)&pv[8]  = *(const float4*)&p_s[jj * PSTR + 8];
        *(float4*)&pv[12] = *(const float4*)&p_s[jj * PSTR + 12];
        #pragma unroll
        for (int r = 0; r < 16; ++r)
            ka[r] = fmaf(pv[r], qv, ka[r]);
    }
    #pragma unroll
    for (int r = 0; r < 16; ++r) {
        int rowg = b * TK_ + i0 + r;
        float kv = keys[rowg * EMB_ + e];
        float fm = ka[r] * kv;
        float d  = ka[r] - kv;
        g_feat[rowg * F2E_ + e]        = fm;
        g_feat[rowg * F2E_ + EMB_ + e] = d * d;
    }
}

// ---------------------------------------------------------------------------
// K3: out[2048,256] = relu(feat[2048,512] @ Wlast[256,512]^T + blast)
// BM=BN=64, BK=32, 256 threads, 4x4 micro-tiles.
// ---------------------------------------------------------------------------
__global__ void gemm_kernel(const float* __restrict__ Wlast,
                            const float* __restrict__ blast,
                            float* __restrict__ out) {
    __shared__ float As[32 * 65];
    __shared__ float Bs[32 * 65];
    int m0 = blockIdx.y * 64;
    int n0 = blockIdx.x * 64;
    int tid = threadIdx.x;
    int tx = tid & 15, ty = tid >> 4;

    float acc[4][4];
    #pragma unroll
    for (int i = 0; i < 4; ++i)
        #pragma unroll
        for (int jq = 0; jq < 4; ++jq) acc[i][jq] = 0.f;

    int lc = tid & 31, lr = tid >> 5;  // k-lane, row-group
    for (int k0 = 0; k0 < F2E_; k0 += 32) {
        #pragma unroll
        for (int r = lr; r < 64; r += 8)
            As[lc * 65 + r] = g_feat[(m0 + r) * F2E_ + k0 + lc];
        #pragma unroll
        for (int r = lr; r < 64; r += 8)
            Bs[lc * 65 + r] = Wlast[(n0 + r) * F2E_ + k0 + lc];
        __syncthreads();
        #pragma unroll
        for (int k = 0; k < 32; ++k) {
            float av[4], bv[4];
            #pragma unroll
            for (int q = 0; q < 4; ++q) av[q] = As[k * 65 + ty * 4 + q];
            #pragma unroll
            for (int q = 0; q < 4; ++q) bv[q] = Bs[k * 65 + tx * 4 + q];
            #pragma unroll
            for (int i = 0; i < 4; ++i)
                #pragma unroll
                for (int jq = 0; jq < 4; ++jq)
                    acc[i][jq] = fmaf(av[i], bv[jq], acc[i][jq]);
        }
        __syncthreads();
    }

    #pragma unroll
    for (int i = 0; i < 4; ++i) {
        int row = m0 + ty * 4 + i;
        float4 o;
        float b0 = blast[n0 + tx * 4 + 0];
        float b1v = blast[n0 + tx * 4 + 1];
        float b2 = blast[n0 + tx * 4 + 2];
        float b3 = blast[n0 + tx * 4 + 3];
        o.x = fmaxf(acc[i][0] + b0, 0.f);
        o.y = fmaxf(acc[i][1] + b1v, 0.f);
        o.z = fmaxf(acc[i][2] + b2, 0.f);
        o.w = fmaxf(acc[i][3] + b3, 0.f);
        *(float4*)&out[row * EMB_ + n0 + tx * 4] = o;
    }
}

// ---------------------------------------------------------------------------
extern "C" void kernel_launch(void* const* d_in, const int* in_sizes, int n_in,
                              void* d_out, int out_size) {
    const float* queries = (const float*)d_in[0];
    const float* keys    = (const float*)d_in[1];
    const float* qmask   = (const float*)d_in[2];
    const float* kmask   = (const float*)d_in[3];
    const float* W1      = (const float*)d_in[4];
    const float* b1      = (const float*)d_in[5];
    const float* W2      = (const float*)d_in[6];
    const float* Wlast   = (const float*)d_in[7];
    const float* blast   = (const float*)d_in[8];
    float* out = (float*)d_out;

    const int smem_attn = (HID_ * TQ_ + 16 * HID_ + TQ_ * PSTR + 104 + 16) * 4;
    cudaFuncSetAttribute(attn_kernel, cudaFuncAttributeMaxDynamicSharedMemorySize,
                         smem_attn);

    prep_gemm<<<dim3(2, (B_ * TK_) / 64, 2), 256>>>(queries, keys, W1, b1);
    attn_kernel<<<dim3(8, B_), 256, smem_attn>>>(queries, keys, qmask, kmask, W2);
    gemm_kernel<<<dim3(EMB_ / 64, (B_ * TK_) / 64), 256>>>(Wlast, blast, out);
}

// round 3
// speedup vs baseline: 1.7152x; 1.3297x over previous
#include <cuda_runtime.h>

#define B_    16
#define TQ_   128
#define TK_   128
#define EMB_  256
#define HID_  100
#define F2E_  512   // 2*EMB

// Scratch (allocation-free rule: __device__ globals)
__device__ float g_A[B_ * TK_ * HID_];        // A[b][i][h]
__device__ float g_Ct[B_ * HID_ * TQ_];       // C^T[b][h][j]  (includes +b1)
__device__ float g_feat[B_ * TK_ * F2E_];     // [row][f]  f<256: mul, f>=256: sub^2

__device__ __forceinline__ float ftanh(float x) {
    float y;
    asm("tanh.approx.f32 %0, %1;" : "=f"(y) : "f"(x));
    return y;
}

#define SSTR 68   // smem k-major stride: 68*4=272 bytes (16B aligned per k row)

// ---------------------------------------------------------------------------
// K1: prep GEMM, double-buffered, LDS.128 compute.
//   side 0: A[row,h]  = keys[row,:]    . W1[h, 0:256]
//   side 1: Ct[b,h,j] = queries[row,:] . W1[h, 256:512] + b1[h]  (row=b*128+j)
// BM=64 rows, BN=64 h, BK=32, 256 threads, 4x4 micro. grid (2, 32, 2).
// ---------------------------------------------------------------------------
__global__ void __launch_bounds__(256) prep_gemm(
        const float* __restrict__ queries,
        const float* __restrict__ keys,
        const float* __restrict__ W1,
        const float* __restrict__ b1) {
    __shared__ __align__(16) float Xs[2][32 * SSTR];
    __shared__ __align__(16) float Ws[2][32 * SSTR];

    int side = blockIdx.z;
    int n0 = blockIdx.x * 64;
    int m0 = blockIdx.y * 64;
    const float* X  = side ? queries : keys;
    const float* Wb = W1 + (side ? EMB_ : 0);

    int tid = threadIdx.x;
    int lc = tid & 31, lr = tid >> 5;
    int tx = tid & 15, ty = tid >> 4;

    float acc[16];
    #pragma unroll
    for (int i = 0; i < 16; ++i) acc[i] = 0.f;

    float rx[8], rw[8];
    // prefetch tile 0
    #pragma unroll
    for (int u = 0; u < 8; ++u)
        rx[u] = X[(m0 + lr + 8 * u) * EMB_ + lc];
    #pragma unroll
    for (int u = 0; u < 8; ++u) {
        int h = n0 + lr + 8 * u;
        rw[u] = (h < HID_) ? Wb[h * F2E_ + lc] : 0.f;
    }
    #pragma unroll
    for (int u = 0; u < 8; ++u) {
        Xs[0][lc * SSTR + lr + 8 * u] = rx[u];
        Ws[0][lc * SSTR + lr + 8 * u] = rw[u];
    }
    __syncthreads();

    const int NT = EMB_ / 32;  // 8
    #pragma unroll 1
    for (int t = 0; t < NT; ++t) {
        if (t + 1 < NT) {
            int k0 = (t + 1) * 32;
            #pragma unroll
            for (int u = 0; u < 8; ++u)
                rx[u] = X[(m0 + lr + 8 * u) * EMB_ + k0 + lc];
            #pragma unroll
            for (int u = 0; u < 8; ++u) {
                int h = n0 + lr + 8 * u;
                rw[u] = (h < HID_) ? Wb[h * F2E_ + k0 + lc] : 0.f;
            }
        }
        const float* Xb = Xs[t & 1];
        const float* Bb = Ws[t & 1];
        #pragma unroll
        for (int k = 0; k < 32; ++k) {
            float4 xv = *(const float4*)&Xb[k * SSTR + ty * 4];
            float4 wv = *(const float4*)&Bb[k * SSTR + tx * 4];
            acc[0]  = fmaf(xv.x, wv.x, acc[0]);
            acc[1]  = fmaf(xv.x, wv.y, acc[1]);
            acc[2]  = fmaf(xv.x, wv.z, acc[2]);
            acc[3]  = fmaf(xv.x, wv.w, acc[3]);
            acc[4]  = fmaf(xv.y, wv.x, acc[4]);
            acc[5]  = fmaf(xv.y, wv.y, acc[5]);
            acc[6]  = fmaf(xv.y, wv.z, acc[6]);
            acc[7]  = fmaf(xv.y, wv.w, acc[7]);
            acc[8]  = fmaf(xv.z, wv.x, acc[8]);
            acc[9]  = fmaf(xv.z, wv.y, acc[9]);
            acc[10] = fmaf(xv.z, wv.z, acc[10]);
            acc[11] = fmaf(xv.z, wv.w, acc[11]);
            acc[12] = fmaf(xv.w, wv.x, acc[12]);
            acc[13] = fmaf(xv.w, wv.y, acc[13]);
            acc[14] = fmaf(xv.w, wv.z, acc[14]);
            acc[15] = fmaf(xv.w, wv.w, acc[15]);
        }
        if (t + 1 < NT) {
            int nb = (t + 1) & 1;
            #pragma unroll
            for (int u = 0; u < 8; ++u) {
                Xs[nb][lc * SSTR + lr + 8 * u] = rx[u];
                Ws[nb][lc * SSTR + lr + 8 * u] = rw[u];
            }
            __syncthreads();
        }
    }

    #pragma unroll
    for (int i = 0; i < 4; ++i) {
        int row = m0 + ty * 4 + i;
        #pragma unroll
        for (int q = 0; q < 4; ++q) {
            int h = n0 + tx * 4 + q;
            if (h < HID_) {
                if (side == 0) {
                    g_A[row * HID_ + h] = acc[i * 4 + q];
                } else {
                    int b = row >> 7, j = row & 127;
                    g_Ct[(b * HID_ + h) * TQ_ + j] = acc[i * 4 + q] + b1[h];
                }
            }
        }
    }
}

// ---------------------------------------------------------------------------
// K2: fused score MLP + softmax + attention + feature build.
// One block per (b, 8-row i-tile): grid (16, 16) = 256 blocks, 256 threads.
// ---------------------------------------------------------------------------
#define ITILE 8
#define PSTR  12

__global__ void __launch_bounds__(256) attn_kernel(
        const float* __restrict__ queries,
        const float* __restrict__ keys,
        const float* __restrict__ qmask,
        const float* __restrict__ kmask,
        const float* __restrict__ W2) {
    extern __shared__ __align__(16) float sm[];
    float* c_s  = sm;                        // 12800
    float* a_s  = c_s + HID_ * TQ_;          // 800
    float* p_s  = a_s + ITILE * HID_;        // 128*12 = 1536
    float* w2_s = p_s + TQ_ * PSTR;          // 104
    float* km_s = w2_s + 104;                // 8

    int b  = blockIdx.y;
    int i0 = blockIdx.x * ITILE;
    int tid = threadIdx.x;

    for (int idx = tid; idx < HID_ * TQ_; idx += 256)
        c_s[idx] = g_Ct[b * HID_ * TQ_ + idx];
    for (int idx = tid; idx < ITILE * HID_; idx += 256)
        a_s[idx] = g_A[(b * TK_ + i0) * HID_ + idx];
    if (tid < HID_)  w2_s[tid] = W2[tid];
    if (tid < ITILE) km_s[tid] = kmask[b * TK_ + i0 + tid];

    int j = tid & 127;        // query position
    int g = tid >> 7;         // i-row parity (0/1)
    float qm = qmask[b * TQ_ + j];
    __syncthreads();

    // ---- phase 1: sim[ii][j] = sum_h tanh(a[ii,h] + c[h,j]) * w2[h]
    float acc[4];
    #pragma unroll
    for (int r = 0; r < 4; ++r) acc[r] = 0.f;
    for (int h = 0; h < HID_; ++h) {
        float cj = c_s[h * TQ_ + j];
        float w  = w2_s[h];
        #pragma unroll
        for (int r = 0; r < 4; ++r) {
            float x = a_s[(g + 2 * r) * HID_ + h] + cj;
            acc[r] = fmaf(w, ftanh(x), acc[r]);
        }
    }
    const float NEGC = -4294967295.0f;  // -2^32 + 1
    #pragma unroll
    for (int r = 0; r < 4; ++r)
        p_s[j * PSTR + (g + 2 * r)] = (qm == 0.0f) ? NEGC : acc[r];
    __syncthreads();

    // ---- phase 2: softmax over j; warp w owns row w (8 warps, 8 rows)
    int warp = tid >> 5, lane = tid & 31;
    {
        int ii = warp;
        float v[4];
        float m = -3.4e38f;
        #pragma unroll
        for (int q = 0; q < 4; ++q) {
            v[q] = p_s[(lane + 32 * q) * PSTR + ii];
            m = fmaxf(m, v[q]);
        }
        #pragma unroll
        for (int off = 16; off; off >>= 1)
            m = fmaxf(m, __shfl_xor_sync(0xffffffffu, m, off));
        float ssum = 0.f;
        #pragma unroll
        for (int q = 0; q < 4; ++q) { v[q] = __expf(v[q] - m); ssum += v[q]; }
        #pragma unroll
        for (int off = 16; off; off >>= 1)
            ssum += __shfl_xor_sync(0xffffffffu, ssum, off);
        float scale = km_s[ii] / ssum;   // fold key_mask scalar into p
        #pragma unroll
        for (int q = 0; q < 4; ++q)
            p_s[(lane + 32 * q) * PSTR + ii] = v[q] * scale;
    }
    __syncthreads();

    // ---- phase 3: keys_attn[ii,e] = sum_j p[ii,j] * q[b,j,e]; then features
    int e = tid;  // 0..255
    float ka[ITILE];
    #pragma unroll
    for (int r = 0; r < ITILE; ++r) ka[r] = 0.f;
    const float* qb = queries + b * TQ_ * EMB_ + e;
    #pragma unroll 4
    for (int jj = 0; jj < TQ_; ++jj) {
        float qv = qb[jj * EMB_];
        float pv[ITILE];
        *(float4*)&pv[0] = *(const float4*)&p_s[jj * PSTR + 0];
        *(float4*)&pv[4] = *(const float4*)&p_s[jj * PSTR + 4];
        #pragma unroll
        for (int r = 0; r < ITILE; ++r)
            ka[r] = fmaf(pv[r], qv, ka[r]);
    }
    #pragma unroll
    for (int r = 0; r < ITILE; ++r) {
        int rowg = b * TK_ + i0 + r;
        float kv = keys[rowg * EMB_ + e];
        float fm = ka[r] * kv;
        float d  = ka[r] - kv;
        g_feat[rowg * F2E_ + e]        = fm;
        g_feat[rowg * F2E_ + EMB_ + e] = d * d;
    }
}

// ---------------------------------------------------------------------------
// K3: out[2048,256] = relu(feat[2048,512] @ Wlast[256,512]^T + blast)
// BM=BN=64, BK=32, 256 threads, 4x4 micro, double-buffered + LDS.128.
// ---------------------------------------------------------------------------
__global__ void __launch_bounds__(256) gemm_kernel(
        const float* __restrict__ Wlast,
        const float* __restrict__ blast,
        float* __restrict__ out) {
    __shared__ __align__(16) float As[2][32 * SSTR];
    __shared__ __align__(16) float Bs[2][32 * SSTR];

    int m0 = blockIdx.y * 64;
    int n0 = blockIdx.x * 64;
    int tid = threadIdx.x;
    int lc = tid & 31, lr = tid >> 5;
    int tx = tid & 15, ty = tid >> 4;

    float acc[16];
    #pragma unroll
    for (int i = 0; i < 16; ++i) acc[i] = 0.f;

    float ra[8], rb[8];
    #pragma unroll
    for (int u = 0; u < 8; ++u)
        ra[u] = g_feat[(m0 + lr + 8 * u) * F2E_ + lc];
    #pragma unroll
    for (int u = 0; u < 8; ++u)
        rb[u] = Wlast[(n0 + lr + 8 * u) * F2E_ + lc];
    #pragma unroll
    for (int u = 0; u < 8; ++u) {
        As[0][lc * SSTR + lr + 8 * u] = ra[u];
        Bs[0][lc * SSTR + lr + 8 * u] = rb[u];
    }
    __syncthreads();

    const int NT = F2E_ / 32;  // 16
    #pragma unroll 1
    for (int t = 0; t < NT; ++t) {
        if (t + 1 < NT) {
            int k0 = (t + 1) * 32;
            #pragma unroll
            for (int u = 0; u < 8; ++u)
                ra[u] = g_feat[(m0 + lr + 8 * u) * F2E_ + k0 + lc];
            #pragma unroll
            for (int u = 0; u < 8; ++u)
                rb[u] = Wlast[(n0 + lr + 8 * u) * F2E_ + k0 + lc];
        }
        const float* Ab = As[t & 1];
        const float* Bb = Bs[t & 1];
        #pragma unroll
        for (int k = 0; k < 32; ++k) {
            float4 av = *(const float4*)&Ab[k * SSTR + ty * 4];
            float4 bv = *(const float4*)&Bb[k * SSTR + tx * 4];
            acc[0]  = fmaf(av.x, bv.x, acc[0]);
            acc[1]  = fmaf(av.x, bv.y, acc[1]);
            acc[2]  = fmaf(av.x, bv.z, acc[2]);
            acc[3]  = fmaf(av.x, bv.w, acc[3]);
            acc[4]  = fmaf(av.y, bv.x, acc[4]);
            acc[5]  = fmaf(av.y, bv.y, acc[5]);
            acc[6]  = fmaf(av.y, bv.z, acc[6]);
            acc[7]  = fmaf(av.y, bv.w, acc[7]);
            acc[8]  = fmaf(av.z, bv.x, acc[8]);
            acc[9]  = fmaf(av.z, bv.y, acc[9]);
            acc[10] = fmaf(av.z, bv.z, acc[10]);
            acc[11] = fmaf(av.z, bv.w, acc[11]);
            acc[12] = fmaf(av.w, bv.x, acc[12]);
            acc[13] = fmaf(av.w, bv.y, acc[13]);
            acc[14] = fmaf(av.w, bv.z, acc[14]);
            acc[15] = fmaf(av.w, bv.w, acc[15]);
        }
        if (t + 1 < NT) {
            int nb = (t + 1) & 1;
            #pragma unroll
            for (int u = 0; u < 8; ++u) {
                As[nb][lc * SSTR + lr + 8 * u] = ra[u];
                Bs[nb][lc * SSTR + lr + 8 * u] = rb[u];
            }
            __syncthreads();
        }
    }

    float4 bb = *(const float4*)&blast[n0 + tx * 4];
    #pragma unroll
    for (int i = 0; i < 4; ++i) {
        int row = m0 + ty * 4 + i;
        float4 o;
        o.x = fmaxf(acc[i * 4 + 0] + bb.x, 0.f);
        o.y = fmaxf(acc[i * 4 + 1] + bb.y, 0.f);
        o.z = fmaxf(acc[i * 4 + 2] + bb.z, 0.f);
        o.w = fmaxf(acc[i * 4 + 3] + bb.w, 0.f);
        *(float4*)&out[row * EMB_ + n0 + tx * 4] = o;
    }
}

// ---------------------------------------------------------------------------
extern "C" void kernel_launch(void* const* d_in, const int* in_sizes, int n_in,
                              void* d_out, int out_size) {
    const float* queries = (const float*)d_in[0];
    const float* keys    = (const float*)d_in[1];
    const float* qmask   = (const float*)d_in[2];
    const float* kmask   = (const float*)d_in[3];
    const float* W1      = (const float*)d_in[4];
    const float* b1      = (const float*)d_in[5];
    const float* W2      = (const float*)d_in[6];
    const float* Wlast   = (const float*)d_in[7];
    const float* blast   = (const float*)d_in[8];
    float* out = (float*)d_out;

    const int smem_attn = (HID_ * TQ_ + ITILE * HID_ + TQ_ * PSTR + 104 + 8) * 4;
    cudaFuncSetAttribute(attn_kernel, cudaFuncAttributeMaxDynamicSharedMemorySize,
                         smem_attn);

    prep_gemm<<<dim3(2, (B_ * TK_) / 64, 2), 256>>>(queries, keys, W1, b1);
    attn_kernel<<<dim3(TK_ / ITILE, B_), 256, smem_attn>>>(queries, keys, qmask,
                                                           kmask, W2);
    gemm_kernel<<<dim3(EMB_ / 64, (B_ * TK_) / 64), 256>>>(Wlast, blast, out);
}

// round 4
// speedup vs baseline: 1.7742x; 1.0344x over previous
#include <cuda_runtime.h>

#define B_    16
#define TQ_   128
#define TK_   128
#define EMB_  256
#define HID_  100
#define F2E_  512   // 2*EMB

// Scratch (allocation-free rule: __device__ globals)
__device__ float g_A[B_ * TK_ * HID_];        // A[b][i][h]
__device__ float g_Ct[B_ * HID_ * TQ_];       // C^T[b][h][j]  (includes +b1)
__device__ float g_feat[B_ * TK_ * F2E_];     // [row][f]  f<256: mul, f>=256: sub^2

__device__ __forceinline__ float ftanh(float x) {
    float y;
    asm("tanh.approx.f32 %0, %1;" : "=f"(y) : "f"(x));
    return y;
}

#define XSTR 36   // smem stride for 32-wide tiles (36*4=144B, 16B aligned)
#define WSTR 68   // smem stride for 64-wide tiles (68*4=272B, 16B aligned)

// ---------------------------------------------------------------------------
// K1: prep GEMM over fused M=4096 (rows 0..2047: keys -> A with W1[:, :256];
//     rows 2048..4095: queries -> Ct with W1[:, 256:] + b1).
// BM=32, BN=64, BK=32, 128 threads, 4x4 micro, double-buffered.
// grid (2 n-tiles, 128 m-tiles) = 256 blocks.
// ---------------------------------------------------------------------------
__global__ void __launch_bounds__(128) prep_gemm(
        const float* __restrict__ queries,
        const float* __restrict__ keys,
        const float* __restrict__ W1,
        const float* __restrict__ b1) {
    __shared__ __align__(16) float Xs[2][32 * XSTR];
    __shared__ __align__(16) float Ws[2][32 * WSTR];

    int m0g = blockIdx.y * 32;             // 0..4064
    int side = m0g >= (B_ * TK_);          // 0: keys, 1: queries
    int m0 = m0g & (B_ * TK_ - 1);         // row within side
    int n0 = blockIdx.x * 64;              // h tile
    const float* X  = side ? queries : keys;
    const float* Wb = W1 + (side ? EMB_ : 0);

    int tid = threadIdx.x;
    int lc = tid & 31, lr = tid >> 5;      // k-lane, row group (0..3)
    int tx = tid & 15, ty = tid >> 4;      // micro col, micro row

    float acc[16];
    #pragma unroll
    for (int i = 0; i < 16; ++i) acc[i] = 0.f;

    float rx[8], rw[16];
    #pragma unroll
    for (int u = 0; u < 8; ++u)
        rx[u] = X[(m0 + lr + 4 * u) * EMB_ + lc];
    #pragma unroll
    for (int u = 0; u < 16; ++u) {
        int h = n0 + lr + 4 * u;
        rw[u] = (h < HID_) ? Wb[h * F2E_ + lc] : 0.f;
    }
    #pragma unroll
    for (int u = 0; u < 8; ++u)
        Xs[0][lc * XSTR + lr + 4 * u] = rx[u];
    #pragma unroll
    for (int u = 0; u < 16; ++u)
        Ws[0][lc * WSTR + lr + 4 * u] = rw[u];
    __syncthreads();

    const int NT = EMB_ / 32;  // 8
    #pragma unroll 1
    for (int t = 0; t < NT; ++t) {
        if (t + 1 < NT) {
            int k0 = (t + 1) * 32;
            #pragma unroll
            for (int u = 0; u < 8; ++u)
                rx[u] = X[(m0 + lr + 4 * u) * EMB_ + k0 + lc];
            #pragma unroll
            for (int u = 0; u < 16; ++u) {
                int h = n0 + lr + 4 * u;
                rw[u] = (h < HID_) ? Wb[h * F2E_ + k0 + lc] : 0.f;
            }
        }
        const float* Xb = Xs[t & 1];
        const float* Bb = Ws[t & 1];
        #pragma unroll
        for (int k = 0; k < 32; ++k) {
            float4 xv = *(const float4*)&Xb[k * XSTR + ty * 4];
            float4 wv = *(const float4*)&Bb[k * WSTR + tx * 4];
            acc[0]  = fmaf(xv.x, wv.x, acc[0]);
            acc[1]  = fmaf(xv.x, wv.y, acc[1]);
            acc[2]  = fmaf(xv.x, wv.z, acc[2]);
            acc[3]  = fmaf(xv.x, wv.w, acc[3]);
            acc[4]  = fmaf(xv.y, wv.x, acc[4]);
            acc[5]  = fmaf(xv.y, wv.y, acc[5]);
            acc[6]  = fmaf(xv.y, wv.z, acc[6]);
            acc[7]  = fmaf(xv.y, wv.w, acc[7]);
            acc[8]  = fmaf(xv.z, wv.x, acc[8]);
            acc[9]  = fmaf(xv.z, wv.y, acc[9]);
            acc[10] = fmaf(xv.z, wv.z, acc[10]);
            acc[11] = fmaf(xv.z, wv.w, acc[11]);
            acc[12] = fmaf(xv.w, wv.x, acc[12]);
            acc[13] = fmaf(xv.w, wv.y, acc[13]);
            acc[14] = fmaf(xv.w, wv.z, acc[14]);
            acc[15] = fmaf(xv.w, wv.w, acc[15]);
        }
        if (t + 1 < NT) {
            int nb = (t + 1) & 1;
            #pragma unroll
            for (int u = 0; u < 8; ++u)
                Xs[nb][lc * XSTR + lr + 4 * u] = rx[u];
            #pragma unroll
            for (int u = 0; u < 16; ++u)
                Ws[nb][lc * WSTR + lr + 4 * u] = rw[u];
            __syncthreads();
        }
    }

    #pragma unroll
    for (int i = 0; i < 4; ++i) {
        int row = m0 + ty * 4 + i;
        #pragma unroll
        for (int q = 0; q < 4; ++q) {
            int h = n0 + tx * 4 + q;
            if (h < HID_) {
                if (side == 0) {
                    g_A[row * HID_ + h] = acc[i * 4 + q];
                } else {
                    int b = row >> 7, j = row & 127;
                    g_Ct[(b * HID_ + h) * TQ_ + j] = acc[i * 4 + q] + b1[h];
                }
            }
        }
    }
}

// ---------------------------------------------------------------------------
// K2: fused score MLP + softmax + attention + feature build.
// One block per (b, 8-row i-tile): grid (16, 16) = 256 blocks, 256 threads.
// ---------------------------------------------------------------------------
#define ITILE 8
#define PSTR  12

__global__ void __launch_bounds__(256) attn_kernel(
        const float* __restrict__ queries,
        const float* __restrict__ keys,
        const float* __restrict__ qmask,
        const float* __restrict__ kmask,
        const float* __restrict__ W2) {
    extern __shared__ __align__(16) float sm[];
    float* c_s  = sm;                        // 12800
    float* a_s  = c_s + HID_ * TQ_;          // 800
    float* p_s  = a_s + ITILE * HID_;        // 128*12 = 1536
    float* w2_s = p_s + TQ_ * PSTR;          // 104
    float* km_s = w2_s + 104;                // 8

    int b  = blockIdx.y;
    int i0 = blockIdx.x * ITILE;
    int tid = threadIdx.x;

    for (int idx = tid; idx < HID_ * TQ_; idx += 256)
        c_s[idx] = g_Ct[b * HID_ * TQ_ + idx];
    for (int idx = tid; idx < ITILE * HID_; idx += 256)
        a_s[idx] = g_A[(b * TK_ + i0) * HID_ + idx];
    if (tid < HID_)  w2_s[tid] = W2[tid];
    if (tid < ITILE) km_s[tid] = kmask[b * TK_ + i0 + tid];

    int j = tid & 127;        // query position
    int g = tid >> 7;         // i-row parity (0/1)
    float qm = qmask[b * TQ_ + j];
    __syncthreads();

    // ---- phase 1: sim[ii][j] = sum_h tanh(a[ii,h] + c[h,j]) * w2[h]
    float acc[4];
    #pragma unroll
    for (int r = 0; r < 4; ++r) acc[r] = 0.f;
    for (int h = 0; h < HID_; ++h) {
        float cj = c_s[h * TQ_ + j];
        float w  = w2_s[h];
        #pragma unroll
        for (int r = 0; r < 4; ++r) {
            float x = a_s[(g + 2 * r) * HID_ + h] + cj;
            acc[r] = fmaf(w, ftanh(x), acc[r]);
        }
    }
    const float NEGC = -4294967295.0f;  // -2^32 + 1
    #pragma unroll
    for (int r = 0; r < 4; ++r)
        p_s[j * PSTR + (g + 2 * r)] = (qm == 0.0f) ? NEGC : acc[r];
    __syncthreads();

    // ---- phase 2: softmax over j; warp w owns row w (8 warps, 8 rows)
    int warp = tid >> 5, lane = tid & 31;
    {
        int ii = warp;
        float v[4];
        float m = -3.4e38f;
        #pragma unroll
        for (int q = 0; q < 4; ++q) {
            v[q] = p_s[(lane + 32 * q) * PSTR + ii];
            m = fmaxf(m, v[q]);
        }
        #pragma unroll
        for (int off = 16; off; off >>= 1)
            m = fmaxf(m, __shfl_xor_sync(0xffffffffu, m, off));
        float ssum = 0.f;
        #pragma unroll
        for (int q = 0; q < 4; ++q) { v[q] = __expf(v[q] - m); ssum += v[q]; }
        #pragma unroll
        for (int off = 16; off; off >>= 1)
            ssum += __shfl_xor_sync(0xffffffffu, ssum, off);
        float scale = km_s[ii] / ssum;   // fold key_mask scalar into p
        #pragma unroll
        for (int q = 0; q < 4; ++q)
            p_s[(lane + 32 * q) * PSTR + ii] = v[q] * scale;
    }
    __syncthreads();

    // ---- phase 3: keys_attn[ii,e] = sum_j p[ii,j] * q[b,j,e]; then features
    int e = tid;  // 0..255
    float ka[ITILE];
    #pragma unroll
    for (int r = 0; r < ITILE; ++r) ka[r] = 0.f;
    const float* qb = queries + b * TQ_ * EMB_ + e;
    #pragma unroll 4
    for (int jj = 0; jj < TQ_; ++jj) {
        float qv = qb[jj * EMB_];
        float pv[ITILE];
        *(float4*)&pv[0] = *(const float4*)&p_s[jj * PSTR + 0];
        *(float4*)&pv[4] = *(const float4*)&p_s[jj * PSTR + 4];
        #pragma unroll
        for (int r = 0; r < ITILE; ++r)
            ka[r] = fmaf(pv[r], qv, ka[r]);
    }
    #pragma unroll
    for (int r = 0; r < ITILE; ++r) {
        int rowg = b * TK_ + i0 + r;
        float kv = keys[rowg * EMB_ + e];
        float fm = ka[r] * kv;
        float d  = ka[r] - kv;
        g_feat[rowg * F2E_ + e]        = fm;
        g_feat[rowg * F2E_ + EMB_ + e] = d * d;
    }
}

// ---------------------------------------------------------------------------
// K3: out[2048,256] = relu(feat[2048,512] @ Wlast[256,512]^T + blast)
// BM=32, BN=64, BK=32, 128 threads, 4x4 micro, double-buffered.
// grid (4 n-tiles, 64 m-tiles) = 256 blocks.
// ---------------------------------------------------------------------------
__global__ void __launch_bounds__(128) gemm_kernel(
        const float* __restrict__ Wlast,
        const float* __restrict__ blast,
        float* __restrict__ out) {
    __shared__ __align__(16) float As[2][32 * XSTR];
    __shared__ __align__(16) float Bs[2][32 * WSTR];

    int m0 = blockIdx.y * 32;
    int n0 = blockIdx.x * 64;
    int tid = threadIdx.x;
    int lc = tid & 31, lr = tid >> 5;
    int tx = tid & 15, ty = tid >> 4;

    float acc[16];
    #pragma unroll
    for (int i = 0; i < 16; ++i) acc[i] = 0.f;

    float ra[8], rb[16];
    #pragma unroll
    for (int u = 0; u < 8; ++u)
        ra[u] = g_feat[(m0 + lr + 4 * u) * F2E_ + lc];
    #pragma unroll
    for (int u = 0; u < 16; ++u)
        rb[u] = Wlast[(n0 + lr + 4 * u) * F2E_ + lc];
    #pragma unroll
    for (int u = 0; u < 8; ++u)
        As[0][lc * XSTR + lr + 4 * u] = ra[u];
    #pragma unroll
    for (int u = 0; u < 16; ++u)
        Bs[0][lc * WSTR + lr + 4 * u] = rb[u];
    __syncthreads();

    const int NT = F2E_ / 32;  // 16
    #pragma unroll 1
    for (int t = 0; t < NT; ++t) {
        if (t + 1 < NT) {
            int k0 = (t + 1) * 32;
            #pragma unroll
            for (int u = 0; u < 8; ++u)
                ra[u] = g_feat[(m0 + lr + 4 * u) * F2E_ + k0 + lc];
            #pragma unroll
            for (int u = 0; u < 16; ++u)
                rb[u] = Wlast[(n0 + lr + 4 * u) * F2E_ + k0 + lc];
        }
        const float* Ab = As[t & 1];
        const float* Bb = Bs[t & 1];
        #pragma unroll
        for (int k = 0; k < 32; ++k) {
            float4 av = *(const float4*)&Ab[k * XSTR + ty * 4];
            float4 bv = *(const float4*)&Bb[k * WSTR + tx * 4];
            acc[0]  = fmaf(av.x, bv.x, acc[0]);
            acc[1]  = fmaf(av.x, bv.y, acc[1]);
            acc[2]  = fmaf(av.x, bv.z, acc[2]);
            acc[3]  = fmaf(av.x, bv.w, acc[3]);
            acc[4]  = fmaf(av.y, bv.x, acc[4]);
            acc[5]  = fmaf(av.y, bv.y, acc[5]);
            acc[6]  = fmaf(av.y, bv.z, acc[6]);
            acc[7]  = fmaf(av.y, bv.w, acc[7]);
            acc[8]  = fmaf(av.z, bv.x, acc[8]);
            acc[9]  = fmaf(av.z, bv.y, acc[9]);
            acc[10] = fmaf(av.z, bv.z, acc[10]);
            acc[11] = fmaf(av.z, bv.w, acc[11]);
            acc[12] = fmaf(av.w, bv.x, acc[12]);
            acc[13] = fmaf(av.w, bv.y, acc[13]);
            acc[14] = fmaf(av.w, bv.z, acc[14]);
            acc[15] = fmaf(av.w, bv.w, acc[15]);
        }
        if (t + 1 < NT) {
            int nb = (t + 1) & 1;
            #pragma unroll
            for (int u = 0; u < 8; ++u)
                As[nb][lc * XSTR + lr + 4 * u] = ra[u];
            #pragma unroll
            for (int u = 0; u < 16; ++u)
                Bs[nb][lc * WSTR + lr + 4 * u] = rb[u];
            __syncthreads();
        }
    }

    float4 bb = *(const float4*)&blast[n0 + tx * 4];
    #pragma unroll
    for (int i = 0; i < 4; ++i) {
        int row = m0 + ty * 4 + i;
        float4 o;
        o.x = fmaxf(acc[i * 4 + 0] + bb.x, 0.f);
        o.y = fmaxf(acc[i * 4 + 1] + bb.y, 0.f);
        o.z = fmaxf(acc[i * 4 + 2] + bb.z, 0.f);
        o.w = fmaxf(acc[i * 4 + 3] + bb.w, 0.f);
        *(float4*)&out[row * EMB_ + n0 + tx * 4] = o;
    }
}

// ---------------------------------------------------------------------------
extern "C" void kernel_launch(void* const* d_in, const int* in_sizes, int n_in,
                              void* d_out, int out_size) {
    const float* queries = (const float*)d_in[0];
    const float* keys    = (const float*)d_in[1];
    const float* qmask   = (const float*)d_in[2];
    const float* kmask   = (const float*)d_in[3];
    const float* W1      = (const float*)d_in[4];
    const float* b1      = (const float*)d_in[5];
    const float* W2      = (const float*)d_in[6];
    const float* Wlast   = (const float*)d_in[7];
    const float* blast   = (const float*)d_in[8];
    float* out = (float*)d_out;

    const int smem_attn = (HID_ * TQ_ + ITILE * HID_ + TQ_ * PSTR + 104 + 8) * 4;
    cudaFuncSetAttribute(attn_kernel, cudaFuncAttributeMaxDynamicSharedMemorySize,
                         smem_attn);

    prep_gemm<<<dim3(2, (2 * B_ * TK_) / 32), 128>>>(queries, keys, W1, b1);
    attn_kernel<<<dim3(TK_ / ITILE, B_), 256, smem_attn>>>(queries, keys, qmask,
                                                           kmask, W2);
    gemm_kernel<<<dim3(EMB_ / 64, (B_ * TK_) / 32), 128>>>(Wlast, blast, out);
}